// round 12
// baseline (speedup 1.0000x reference)
#include <cuda_runtime.h>
#include <math.h>
#include <stdint.h>

// Problem dims
constexpr int NB = 128;    // batch
constexpr int NL = 1024;   // seq len
constexpr int NE = 64;     // embed
constexpr int NH = 512;    // hidden
constexpr int NV = 96;     // vocab

// RNN kernel config: warp-specialized, per-row pipelined L2 exchange
constexpr int CS   = 8;          // CTAs per group (column slices)
constexpr int RPC  = 8;          // batch rows per group
constexpr int NCL  = NB / RPC;   // 16 groups
constexpr int GRNN = NCL * CS;   // 128 CTAs
constexpr int NCT  = 512;        // compute threads (16 warps)
constexpr int NRT  = 64;         // reducer threads (2 warps)
constexpr int TRNN = NCT + NRT;  // 576 threads
constexpr int KS   = NH / CS;    // 64 k/cols owned per CTA
constexpr int POSTS = 128;       // posts per row-step: 16 warps x 8 CTAs

// SMEM: prologue scratch (NV*NE + NE*KS = 10240 f) overlays steady state
// (sproj 6144 f + sh 2*8*64=1024 f).
constexpr int SM_PROJ = NV * KS;
constexpr int SM_SH   = 2 * RPC * KS;
constexpr int RNN_SMEM_BYTES = (NV * NE + NE * KS) * 4 + 64;  // 41KB

// Logits kernel config (persistent, 8 rows/warp)
constexpr int LG_GRID = 148;
constexpr int LG_TILE = 128;
constexpr int LG_NTILES = NB * NL / LG_TILE;
constexpr int SMEM_LOG_BYTES = (NH / 2) * NV * 8; // 196608 B

// Scratch (device globals: allocation-free rule)
__device__ float g_hs[(size_t)NB * NL * NH];          // 256 MB: all h_t
__device__ float g_part[2 * NCL * CS * RPC * NH];     // 2 MB partial mailboxes
__device__ int   g_cnt[2 * NCL * RPC];                // 256 row counters (zero-init)

// ---------------------------------------------------------------------------
// Helpers
// ---------------------------------------------------------------------------
__device__ __forceinline__ unsigned long long packf2(float lo, float hi) {
    return (unsigned long long)__float_as_uint(lo) |
           ((unsigned long long)__float_as_uint(hi) << 32);
}
__device__ __forceinline__ float f2lo(unsigned long long v) {
    return __uint_as_float((uint32_t)v);
}
__device__ __forceinline__ float f2hi(unsigned long long v) {
    return __uint_as_float((uint32_t)(v >> 32));
}
#define FMA2(acc, a, b) \
    asm volatile("fma.rn.f32x2 %0, %1, %2, %0;" : "+l"(acc) : "l"(a), "l"(b))

__device__ __forceinline__ int ld_acq(const int* p) {
    int v;
    asm volatile("ld.acquire.gpu.global.s32 %0, [%1];" : "=r"(v) : "l"(p) : "memory");
    return v;
}
__device__ __forceinline__ int ld_rlx(const int* p) {
    int v;
    asm volatile("ld.relaxed.gpu.global.s32 %0, [%1];" : "=r"(v) : "l"(p) : "memory");
    return v;
}
__device__ __forceinline__ void red_rel_add1(int* p) {
    int one = 1;
    asm volatile("red.release.gpu.global.add.s32 [%0], %1;" :: "l"(p), "r"(one) : "memory");
}
#define BAR_SYNC(id)   asm volatile("bar.sync %0, %1;"   :: "r"(id), "r"(TRNN) : "memory")
#define BAR_ARRIVE(id) asm volatile("bar.arrive %0, %1;" :: "r"(id), "r"(TRNN) : "memory")

// Row counters cleared for the NEXT call (graph replays reuse them).
__global__ void clear_cnt_kernel() { g_cnt[threadIdx.x] = 0; }

// ---------------------------------------------------------------------------
// Kernel 1: warp-specialized recurrence.
// 16 compute warps: per row r: bar.sync(1+r) [h ready] -> 32 FMA2 from
// sh[pb][r] -> coalesced STG partial -> syncwarp -> lane0 red.release on
// cnt[pb][cl][r]. 2 reducer warps: 4 rows in flight: spin counters (128
// posts), acquire, 32 ldcg partial reads, +proj+tanh, write sh[t&1][r] +
// g_hs, bar.arrive(1+r). Exchange latency hides behind the other rows.
// ---------------------------------------------------------------------------
__global__ __launch_bounds__(TRNN, 1)
void rnn8_kernel(const void* __restrict__ xraw,
                 const float* __restrict__ h0,
                 const float* __restrict__ Whh,
                 const float* __restrict__ emb,
                 const float* __restrict__ Wxh,
                 const float* __restrict__ bh,
                 float* __restrict__ finalh) {
    extern __shared__ float sm[];
    float* sproj = sm;                 // [NV][KS]      (steady state)
    float* sh    = sm + SM_PROJ;       // [2][RPC][KS]  (double-buffered h)

    const int tid     = threadIdx.x;
    const int rank    = blockIdx.x & (CS - 1);
    const int cl      = blockIdx.x >> 3;
    const int row0    = cl * RPC;
    const int colbase = rank * KS;

    // Detect x dtype: int64 (odd int32 words all zero) vs int32.
    const int* xi = (const int*)xraw;
    bool is64 = true;
    for (int i = 1; i < 128; i += 2) {
        if (xi[i] != 0) { is64 = false; break; }
    }
    const long long* x64 = (const long long*)xraw;
    const int*       x32 = (const int*)xraw;

    // ---- fused proj (512 compute threads do the math; all 576 stage) ----
    {
        float* semb = sm;            // [NV][NE]  6144 f (scratch, = sproj region)
        float* swx  = sm + NV * NE;  // [NE][KS]  4096 f (scratch)
        for (int i = tid; i < NV * NE; i += TRNN) semb[i] = emb[i];
        for (int i = tid; i < NE * KS; i += TRNN) {
            int e = i >> 6, c = i & (KS - 1);
            swx[i] = Wxh[e * NH + colbase + c];
        }
        __syncthreads();
        float pr[NV * KS / NCT];   // 12 outputs per compute thread
        if (tid < NCT) {
            #pragma unroll
            for (int o = 0; o < NV * KS / NCT; o++) {
                int idx = o * NCT + tid;
                int v = idx >> 6, c = idx & (KS - 1);
                float acc = bh[colbase + c];
                #pragma unroll 8
                for (int e = 0; e < NE; e++) acc += semb[v * NE + e] * swx[e * KS + c];
                pr[o] = acc;
            }
        }
        __syncthreads();
        if (tid < NCT) {
            #pragma unroll
            for (int o = 0; o < NV * KS / NCT; o++) sproj[o * NCT + tid] = pr[o];
            // h_{-1} into sh[0]
            sh[(tid >> 6) * KS + (tid & (KS - 1))] =
                h0[(size_t)(row0 + (tid >> 6)) * NH + colbase + (tid & (KS - 1))];
        }
        __syncthreads();
    }

    constexpr int PB_MAIL = NCL * CS * RPC * NH;   // mail pb stride (floats)
    constexpr int PB_CNT  = NCL * RPC;             // cnt pb stride

    if (tid < NCT) {
        // ================= COMPUTE WARPS =================
        const int j    = tid;            // global column 0..511
        const int lane = tid & 31;

        // W_hh slice -> registers, packed (W[cb+2p][j], W[cb+2p+1][j])
        unsigned long long wreg[KS / 2];
        {
            const float* Wb = Whh + (size_t)colbase * NH + j;
            #pragma unroll
            for (int p = 0; p < KS / 2; p++)
                wreg[p] = packf2(Wb[(size_t)(2 * p) * NH], Wb[(size_t)(2 * p + 1) * NH]);
        }

        float* mybase = g_part + ((size_t)(cl * CS + rank) * RPC) * NH + j;
        int*   cbase  = g_cnt + cl * RPC;

        for (int t = 0; t < NL; t++) {
            const int pb = t & 1;
            float* pd = mybase + pb * PB_MAIL;
            const float* shb = sh + pb * RPC * KS;
            #pragma unroll 1
            for (int r = 0; r < RPC; r++) {
                if (t > 0) BAR_SYNC(1 + r);          // wait h_{t-1}[r] in sh
                unsigned long long a0 = 0ull, a1 = 0ull;
                const float* shr = shb + r * KS;
                #pragma unroll
                for (int p2 = 0; p2 < KS / 4; p2++) {
                    ulonglong2 hh = *(const ulonglong2*)&shr[p2 * 4];
                    FMA2(a0, wreg[2 * p2],     hh.x);
                    FMA2(a1, wreg[2 * p2 + 1], hh.y);
                }
                float v = (f2lo(a0) + f2hi(a0)) + (f2lo(a1) + f2hi(a1));
                __stcg(pd + r * NH, v);
                __syncwarp();
                if (lane == 0) red_rel_add1(cbase + pb * PB_CNT + r);
            }
        }
    } else {
        // ================= REDUCER WARPS =================
        const int rid = tid - NCT;       // 0..63 = column within slice
        for (int t = 1; t <= NL; t++) {
            const int pbp    = (t - 1) & 1;
            const int target = POSTS * (((t - 1) >> 1) + 1);
            const int pbw    = t & 1;
            const int* cb    = g_cnt + pbp * PB_CNT + cl * RPC;
            const float* mb  = g_part + (size_t)pbp * PB_MAIL
                             + (size_t)cl * CS * RPC * NH + colbase + rid;
            #pragma unroll
            for (int rb = 0; rb < 2; rb++) {
                const int r0 = rb * 4;
                // token loads (uniform per row; broadcast in LSU)
                int tk[4];
                #pragma unroll
                for (int q = 0; q < 4; q++) {
                    size_t ix = (size_t)(row0 + r0 + q) * NL + (t - 1);
                    tk[q] = is64 ? (int)x64[ix] : x32[ix];
                }
                // relaxed spin on 4 counters (concurrent), then acquire
                for (;;) {
                    int v0 = ld_rlx(cb + r0 + 0), v1 = ld_rlx(cb + r0 + 1);
                    int v2 = ld_rlx(cb + r0 + 2), v3 = ld_rlx(cb + r0 + 3);
                    if (v0 >= target && v1 >= target && v2 >= target && v3 >= target) break;
                }
                #pragma unroll
                for (int q = 0; q < 4; q++) (void)ld_acq(cb + r0 + q);
                // gather 8 partials per row (32 loads in flight)
                float s[4] = {0.f, 0.f, 0.f, 0.f};
                #pragma unroll
                for (int src = 0; src < CS; src++) {
                    const float* ms = mb + (size_t)src * RPC * NH;
                    #pragma unroll
                    for (int q = 0; q < 4; q++)
                        s[q] += __ldcg(ms + (size_t)(r0 + q) * NH);
                }
                #pragma unroll
                for (int q = 0; q < 4; q++) {
                    const int row = r0 + q;
                    float h = tanhf(s[q] + sproj[tk[q] * KS + rid]);
                    g_hs[((size_t)(row0 + row) * NL + (t - 1)) * NH + colbase + rid] = h;
                    if (t < NL) {
                        sh[(pbw * RPC + row) * KS + rid] = h;
                        BAR_ARRIVE(1 + row);
                    } else if (finalh) {
                        finalh[(row0 + row) * NH + colbase + rid] = h;
                    }
                }
            }
        }
    }
}

// ---------------------------------------------------------------------------
// Kernel 2: persistent logits GEMM (unchanged: measured 352us).
// ---------------------------------------------------------------------------
__global__ __launch_bounds__(512, 1)
void logits3_kernel(const float* __restrict__ fcw,
                    const float* __restrict__ fcb,
                    float* __restrict__ out) {
    extern __shared__ unsigned long long spk[];  // [NH/2][NV] packed pairs
    const int tid  = threadIdx.x;
    const int lane = tid & 31;
    const int warp = tid >> 5;

    for (int i = tid; i < (NH / 2) * NV; i += 512) {
        int k2 = i / NV, c = i - k2 * NV;
        spk[i] = packf2(fcw[(2 * k2) * NV + c], fcw[(2 * k2 + 1) * NV + c]);
    }
    float b[3];
    #pragma unroll
    for (int g = 0; g < 3; g++) b[g] = fcb[g * 32 + lane];
    __syncthreads();

    for (int tile = blockIdx.x; tile < LG_NTILES; tile += gridDim.x) {
        const size_t row0 = (size_t)tile * LG_TILE + warp * 8;
        const float* hsr = g_hs + row0 * NH;

        unsigned long long acc[8][3];
        #pragma unroll
        for (int i = 0; i < 8; i++)
            #pragma unroll
            for (int g = 0; g < 3; g++) acc[i][g] = 0ull;

        for (int k4 = 0; k4 < NH / 4; k4++) {
            ulonglong2 hp[8];
            #pragma unroll
            for (int i = 0; i < 8; i++)
                hp[i] = *(const ulonglong2*)&hsr[(size_t)i * NH + 4 * k4];
            #pragma unroll
            for (int g = 0; g < 3; g++) {
                unsigned long long w0 = spk[(2 * k4) * NV + g * 32 + lane];
                unsigned long long w1 = spk[(2 * k4 + 1) * NV + g * 32 + lane];
                #pragma unroll
                for (int i = 0; i < 8; i++) {
                    FMA2(acc[i][g], hp[i].x, w0);
                    FMA2(acc[i][g], hp[i].y, w1);
                }
            }
        }
        #pragma unroll
        for (int i = 0; i < 8; i++)
            #pragma unroll
            for (int g = 0; g < 3; g++) {
                float s = f2lo(acc[i][g]) + f2hi(acc[i][g]) + b[g];
                out[(row0 + i) * NV + g * 32 + lane] = s;
            }
    }
}

// ---------------------------------------------------------------------------
// Launch
// ---------------------------------------------------------------------------
extern "C" void kernel_launch(void* const* d_in, const int* in_sizes, int n_in,
                              void* d_out, int out_size) {
    const void*  x      = d_in[0];                 // [B,L] int64 or int32
    const float* hidden = (const float*)d_in[1];   // [B,H]
    const float* emb    = (const float*)d_in[2];   // [V,E]
    const float* Wxh    = (const float*)d_in[3];   // [E,H]
    const float* Whh    = (const float*)d_in[4];   // [H,H]
    const float* bh     = (const float*)d_in[5];   // [H]
    const float* fcw    = (const float*)d_in[6];   // [H,V]
    const float* fcb    = (const float*)d_in[7];   // [V]

    float* out = (float*)d_out;                    // logits [B,L,V] ...
    const size_t logitsN = (size_t)NB * NL * NV;
    float* finalh = (out_size >= (int)(logitsN + (size_t)NB * NH))
                        ? out + logitsN : nullptr; // ... then final_h [B,H]

    cudaFuncSetAttribute(rnn8_kernel,
                         cudaFuncAttributeMaxDynamicSharedMemorySize,
                         RNN_SMEM_BYTES);
    cudaFuncSetAttribute(logits3_kernel,
                         cudaFuncAttributeMaxDynamicSharedMemorySize,
                         SMEM_LOG_BYTES);

    rnn8_kernel<<<GRNN, TRNN, RNN_SMEM_BYTES>>>(x, hidden, Whh, emb, Wxh, bh, finalh);
    logits3_kernel<<<LG_GRID, 512, SMEM_LOG_BYTES>>>(fcw, fcb, out);
    clear_cnt_kernel<<<1, 2 * NCL * RPC>>>();
}